// round 11
// baseline (speedup 1.0000x reference)
#include <cuda_runtime.h>
#include <cuda_bf16.h>
#include <math.h>

#define BATCH 2
#define LEN   2048
#define DIM   1024
#define KH    32
#define MM    4
#define HH    32
#define AHN   4
#define DHN   28
#define CKN   4
#define TOT   2208
#define ROWS  (BATCH*LEN)          // 4096
#define NCH   64                   // chunks along L
#define LCH   32                   // chunk length
#define NUNIT (BATCH*KH*NCH)       // 4096 warp units
#define CSS   260                  // chunk-state stride (256 re/im + den + pad)
#define R2    (ROWS*KH)            // 131072 rows for GEMM2
#define PI3   1.0471975511965976f

// ---------------- scratch (device globals; no cudaMalloc allowed) ------------
static __device__ float g_Z[ROWS*TOT];        // 36.2 MB  post-GEMM1 / pre-conv
static __device__ float g_XV[ROWS*DIM];       // 16.8 MB  x_val
static __device__ float g_GATE[ROWS*DIM];     // 16.8 MB  silu gate
static __device__ float g_PW[ROWS*KH];        //  0.5 MB  p * time_weight
static __device__ float g_TH[ROWS*KH*MM];     //  2.1 MB  theta_dyn
static __device__ float g_CS[NUNIT*CSS];      //  4.3 MB  chunk sums / offsets
static __device__ float g_MG[(size_t)NUNIT*LCH*256]; // 134 MB merged pw*cos|pw*sin
static __device__ float g_RENIM[(size_t)R2*256];     // 134 MB normalized [ren|imn]
static __device__ float g_YG[ROWS*DIM];       // 16.8 MB  y1 * gate

// ---------------- SGEMM 128x128x8, 256 thr, 8x8 microtile, double-buffered --
// selA==0 : A = Ain (param),  C = g_Z     (GEMM1: x @ W_in)
// selA==1 : A = g_YG,         C = Cin     (GEMM3: (y*gate) @ W_out)
__global__ __launch_bounds__(256, 2)
void sgemm128(const float* __restrict__ Ain, const float* __restrict__ B,
              float* __restrict__ Cin, int selA, int M, int N, int Kd)
{
    const float* A = selA ? (const float*)g_YG : Ain;
    float*       C = selA ? Cin : (float*)g_Z;

    __shared__ float As[2][8][128];
    __shared__ float Bs[2][8][128];

    const int tid = threadIdx.x;
    const int bm  = blockIdx.y * 128;
    const int bn  = blockIdx.x * 128;

    const int arow = tid >> 1;          // 0..127
    const int acol = (tid & 1) << 2;    // 0 or 4
    const int brow = tid >> 5;          // 0..7
    const int bcol = (tid & 31) << 2;   // 0..124

    const int tx = tid & 15;
    const int ty = tid >> 4;

    const float* Ag = A + (size_t)(bm + arow) * Kd + acol;
    const float* Bg = B + (size_t)brow * N + bn + bcol;
    const bool bvalid = (bn + bcol) < N;

    float acc[8][8];
#pragma unroll
    for (int i = 0; i < 8; i++)
#pragma unroll
        for (int j = 0; j < 8; j++) acc[i][j] = 0.0f;

    float4 aR = *(const float4*)Ag;
    float4 bR = bvalid ? *(const float4*)Bg : make_float4(0.f,0.f,0.f,0.f);

    int buf = 0;
    As[0][acol+0][arow] = aR.x;
    As[0][acol+1][arow] = aR.y;
    As[0][acol+2][arow] = aR.z;
    As[0][acol+3][arow] = aR.w;
    *(float4*)&Bs[0][brow][bcol] = bR;
    __syncthreads();

    const int nk = Kd >> 3;
    for (int kt = 0; kt < nk; kt++) {
        if (kt + 1 < nk) {
            aR = *(const float4*)(Ag + (kt + 1) * 8);
            bR = bvalid ? *(const float4*)(Bg + (size_t)(kt + 1) * 8 * N)
                        : make_float4(0.f,0.f,0.f,0.f);
        }
#pragma unroll
        for (int kk = 0; kk < 8; kk++) {
            float4 a0 = *(const float4*)&As[buf][kk][ty*8];
            float4 a1 = *(const float4*)&As[buf][kk][ty*8+4];
            float4 b0 = *(const float4*)&Bs[buf][kk][tx*8];
            float4 b1 = *(const float4*)&Bs[buf][kk][tx*8+4];
            float av[8] = {a0.x,a0.y,a0.z,a0.w,a1.x,a1.y,a1.z,a1.w};
            float bv[8] = {b0.x,b0.y,b0.z,b0.w,b1.x,b1.y,b1.z,b1.w};
#pragma unroll
            for (int i = 0; i < 8; i++)
#pragma unroll
                for (int j = 0; j < 8; j++)
                    acc[i][j] = fmaf(av[i], bv[j], acc[i][j]);
        }
        if (kt + 1 < nk) {
            int nb = buf ^ 1;
            As[nb][acol+0][arow] = aR.x;
            As[nb][acol+1][arow] = aR.y;
            As[nb][acol+2][arow] = aR.z;
            As[nb][acol+3][arow] = aR.w;
            *(float4*)&Bs[nb][brow][bcol] = bR;
            __syncthreads();
            buf = nb;
        }
    }

#pragma unroll
    for (int i = 0; i < 8; i++) {
        int row = bm + ty*8 + i;
        float* Cp = C + (size_t)row * N + bn + tx*8;
        if (bn + tx*8 < N)
            *(float4*)Cp = make_float4(acc[i][0],acc[i][1],acc[i][2],acc[i][3]);
        if (bn + tx*8 + 4 < N)
            *(float4*)(Cp+4) = make_float4(acc[i][4],acc[i][5],acc[i][6],acc[i][7]);
    }
}

// ---------------- conv(CK=4) + activations + routing ------------------------
__global__ void conv_act_kernel(const float* __restrict__ mask,
        const float* __restrict__ conv_w, const float* __restrict__ conv_b,
        const float* __restrict__ tbase,  const float* __restrict__ trs,
        const float* __restrict__ decay,  const float* __restrict__ anchor,
        const float* __restrict__ score)
{
    int c = blockIdx.x * blockDim.x + threadIdx.x;
    int r = blockIdx.y;
    if (c >= TOT) return;
    int l = r & (LEN - 1);

    float acc = conv_b[c];
#pragma unroll
    for (int t = 0; t < CKN; t++) {
        int ls = l - (CKN - 1) + t;
        if (ls >= 0)
            acc = fmaf(g_Z[(size_t)(r - (CKN - 1) + t) * TOT + c],
                       conv_w[t * TOT + c], acc);
    }
    float mk = mask[r];

    if (c < DIM) {
        g_XV[(size_t)r * DIM + c] = acc * mk;
    } else if (c < 2*DIM) {
        float sg = 1.0f / (1.0f + __expf(-acc));
        g_GATE[(size_t)r * DIM + (c - DIM)] = acc * sg;
    } else if (c < 2*DIM + KH) {
        int k = c - 2*DIM;
        float ss = acc * mk;
        float sc = score[k] * ss;
        sc = fminf(fmaxf(sc, -20.0f), 20.0f);
        float p = __expf(sc) * mk;
        float w;
        if (k < DHN) {
            float sl = log1pf(__expf(decay[k]));          // softplus
            w = __expf(-sl * (float)(LEN - 1 - l));
        } else {
            float sl = log1pf(__expf(anchor[k - DHN]));
            w = __expf(-sl * (float)l);
        }
        g_PW[r * KH + k] = p * w;
    } else {
        int i = c - (2*DIM + KH);                          // i = k*4 + m
        int k = i >> 2;
        float td = acc / (1.0f + fabsf(acc));
        g_TH[(size_t)r * (KH*MM) + i] = fmaf(trs[k] * td, PI3, tbase[i]);
    }
}

// ---------------- scan pass 1: chunk sums + merged-term store ---------------
// One warp per (b,k,chunk). Computes pw*cos/pw*sin once, stores them to g_MG
// for pass 3 (which previously recomputed all sincos — MUFU-bound).
__global__ void scan_pass1()
{
    int wid  = threadIdx.x >> 5;
    int lane = threadIdx.x & 31;
    int u = blockIdx.x * 8 + wid;       // 0..4095
    int bk = u >> 6;
    int chunk = u & (NCH - 1);
    int b = bk >> 5;
    int k = bk & 31;
    int h = lane;

    float are[4] = {0,0,0,0}, aim[4] = {0,0,0,0}, ad = 0.f;
    int l0 = chunk * LCH;
    const float* xvp = g_XV + (size_t)(b*LEN + l0) * DIM + k*HH + h;
    const float* thp = g_TH + (size_t)(b*LEN + l0) * (KH*MM) + k*MM;
    const float* pwp = g_PW + (size_t)(b*LEN + l0) * KH + k;
    float* mg = g_MG + (size_t)u * LCH * 256;

    for (int i = 0; i < LCH; i++) {
        float xv = xvp[(size_t)i * DIM];
        float4 th = *(const float4*)(thp + (size_t)i * (KH*MM));
        float pw = pwp[(size_t)i * KH];
        float s0,c0,s1,c1,s2,c2,s3,c3;
        __sincosf(xv*th.x, &s0, &c0);
        __sincosf(xv*th.y, &s1, &c1);
        __sincosf(xv*th.z, &s2, &c2);
        __sincosf(xv*th.w, &s3, &c3);
        float r0 = pw*c0, r1 = pw*c1, r2 = pw*c2, r3 = pw*c3;
        float i0 = pw*s0, i1 = pw*s1, i2 = pw*s2, i3 = pw*s3;
        are[0]+=r0; are[1]+=r1; are[2]+=r2; are[3]+=r3;
        aim[0]+=i0; aim[1]+=i1; aim[2]+=i2; aim[3]+=i3;
        ad += pw;
        float* mrow = mg + (size_t)i * 256;
        *(float4*)(mrow + h*4)       = make_float4(r0,r1,r2,r3);
        *(float4*)(mrow + 128 + h*4) = make_float4(i0,i1,i2,i3);
    }
    float* cs = g_CS + (size_t)u * CSS;
    *(float4*)(cs + h*4)       = make_float4(are[0],are[1],are[2],are[3]);
    *(float4*)(cs + 128 + h*4) = make_float4(aim[0],aim[1],aim[2],aim[3]);
    if (h == 0) cs[256] = ad;
}

// ---------------- scan pass 2: exclusive prefix over chunks (MLP) -----------
__global__ void scan_pass2()
{
    int bk = blockIdx.x;       // 0..63
    int j  = threadIdx.x;      // channel 0..256 (256 = den)
    if (j >= 257) return;
    float s = 0.f;
    float* base = g_CS + (size_t)bk * NCH * CSS + j;
#pragma unroll
    for (int c0 = 0; c0 < NCH; c0 += 8) {
        float v[8];
#pragma unroll
        for (int i = 0; i < 8; i++) v[i] = base[(size_t)(c0 + i) * CSS];
#pragma unroll
        for (int i = 0; i < 8; i++) {
            float t = v[i];
            base[(size_t)(c0 + i) * CSS] = s;
            s += t;
        }
    }
}

// ---------------- scan pass 3: stream merged terms, normalize, emit ---------
__global__ void scan_pass3(const float* __restrict__ nscale)
{
    int wid  = threadIdx.x >> 5;
    int lane = threadIdx.x & 31;
    int u = blockIdx.x * 8 + wid;
    int bk = u >> 6;
    int chunk = u & (NCH - 1);
    int b = bk >> 5;
    int k = bk & 31;
    int h = lane;

    float* cs = g_CS + (size_t)u * CSS;
    float4 r4 = *(const float4*)(cs + h*4);
    float4 i4 = *(const float4*)(cs + 128 + h*4);
    float are[4] = {r4.x, r4.y, r4.z, r4.w};
    float aim[4] = {i4.x, i4.y, i4.z, i4.w};
    float ad = cs[256];

    float4 nsr = *(const float4*)(nscale + h*4);
    float4 nsi = *(const float4*)(nscale + 128 + h*4);

    int l0 = chunk * LCH;
    const float* pwp = g_PW + (size_t)(b*LEN + l0) * KH + k;
    const float* mg = g_MG + (size_t)u * LCH * 256;

    for (int i = 0; i < LCH; i++) {
        int l = l0 + i;
        const float* mrow = mg + (size_t)i * 256;
        float4 mr = *(const float4*)(mrow + h*4);
        float4 mi = *(const float4*)(mrow + 128 + h*4);
        float pw = pwp[(size_t)i * KH];
        are[0]+=mr.x; are[1]+=mr.y; are[2]+=mr.z; are[3]+=mr.w;
        aim[0]+=mi.x; aim[1]+=mi.y; aim[2]+=mi.z; aim[3]+=mi.w;
        ad += pw;

        float invd = __fdividef(1.0f, fmaxf(ad, 1e-4f));
        float re0 = are[0]*invd, re1 = are[1]*invd, re2 = are[2]*invd, re3 = are[3]*invd;
        float im0 = aim[0]*invd, im1 = aim[1]*invd, im2 = aim[2]*invd, im3 = aim[3]*invd;

        float msq = re0*re0;
        msq = fmaf(re1,re1,msq); msq = fmaf(re2,re2,msq); msq = fmaf(re3,re3,msq);
        msq = fmaf(im0,im0,msq); msq = fmaf(im1,im1,msq);
        msq = fmaf(im2,im2,msq); msq = fmaf(im3,im3,msq);
#pragma unroll
        for (int off = 16; off >= 1; off >>= 1)
            msq += __shfl_xor_sync(0xffffffffu, msq, off);
        float rsq = rsqrtf(msq * (1.0f/256.0f) + 1e-5f);

        float* outp = g_RENIM + ((size_t)(b*LEN + l) * KH + k) * 256;
        *(float4*)(outp + h*4) = make_float4(re0*rsq*nsr.x, re1*rsq*nsr.y,
                                             re2*rsq*nsr.z, re3*rsq*nsr.w);
        *(float4*)(outp + 128 + h*4) = make_float4(im0*rsq*nsi.x, im1*rsq*nsi.y,
                                                   im2*rsq*nsi.z, im3*rsq*nsi.w);
    }
}

// ---------------- GEMM2: [ren|imn](131072x256) @ [Wre;Wim](256x32), *gate ---
__global__ __launch_bounds__(256)
void gemm2_kernel(const float* __restrict__ Wre, const float* __restrict__ Wim)
{
    __shared__ float Ws[256*32];     // full stacked weight, 32 KB
    __shared__ float As[128*36];     // 128 rows x 32 k, padded

    int tid = threadIdx.x;
    int row0 = blockIdx.x * 128;

    for (int i = tid*4; i < 8192; i += 1024) {
        float4 v = (i < 4096) ? *(const float4*)(Wre + i)
                              : *(const float4*)(Wim + i - 4096);
        *(float4*)&Ws[i] = v;
    }

    int lrow = tid & 127;
    int kq   = tid >> 7;       // 0..1
    int tx   = tid & 7;        // col group: cols tx*4..+3
    int trow = tid >> 3;       // 0..31 -> rows trow*4..+3

    float acc[4][4];
#pragma unroll
    for (int e = 0; e < 4; e++)
#pragma unroll
        for (int q = 0; q < 4; q++) acc[e][q] = 0.0f;

    const float* Ag = g_RENIM + (size_t)(row0 + lrow) * 256;
    __syncthreads();

    for (int kc = 0; kc < 8; kc++) {
#pragma unroll
        for (int q = 0; q < 4; q++) {
            int kidx = kq*4 + q;                       // 0..7
            float4 v = *(const float4*)(Ag + kc*32 + kidx*4);
            *(float4*)&As[lrow*36 + kidx*4] = v;
        }
        __syncthreads();
#pragma unroll
        for (int kk = 0; kk < 32; kk++) {
            float4 w = *(const float4*)&Ws[(kc*32 + kk)*32 + tx*4];
            float a0 = As[(trow*4+0)*36 + kk];
            float a1 = As[(trow*4+1)*36 + kk];
            float a2 = As[(trow*4+2)*36 + kk];
            float a3 = As[(trow*4+3)*36 + kk];
            acc[0][0]=fmaf(a0,w.x,acc[0][0]); acc[0][1]=fmaf(a0,w.y,acc[0][1]);
            acc[0][2]=fmaf(a0,w.z,acc[0][2]); acc[0][3]=fmaf(a0,w.w,acc[0][3]);
            acc[1][0]=fmaf(a1,w.x,acc[1][0]); acc[1][1]=fmaf(a1,w.y,acc[1][1]);
            acc[1][2]=fmaf(a1,w.z,acc[1][2]); acc[1][3]=fmaf(a1,w.w,acc[1][3]);
            acc[2][0]=fmaf(a2,w.x,acc[2][0]); acc[2][1]=fmaf(a2,w.y,acc[2][1]);
            acc[2][2]=fmaf(a2,w.z,acc[2][2]); acc[2][3]=fmaf(a2,w.w,acc[2][3]);
            acc[3][0]=fmaf(a3,w.x,acc[3][0]); acc[3][1]=fmaf(a3,w.y,acc[3][1]);
            acc[3][2]=fmaf(a3,w.z,acc[3][2]); acc[3][3]=fmaf(a3,w.w,acc[3][3]);
        }
        __syncthreads();
    }

#pragma unroll
    for (int e = 0; e < 4; e++) {
        size_t R = (size_t)row0 + trow*4 + e;
        float4 g = *(const float4*)(g_GATE + R*32 + tx*4);   // gate, flat view
        *(float4*)(g_YG + R*32 + tx*4) =
            make_float4(acc[e][0]*g.x, acc[e][1]*g.y, acc[e][2]*g.z, acc[e][3]*g.w);
    }
}

// ---------------- launch -----------------------------------------------------
extern "C" void kernel_launch(void* const* d_in, const int* in_sizes, int n_in,
                              void* d_out, int out_size)
{
    (void)in_sizes; (void)n_in; (void)out_size;
    const float* x      = (const float*)d_in[0];
    const float* mask   = (const float*)d_in[1];
    const float* W_in   = (const float*)d_in[2];
    const float* conv_w = (const float*)d_in[3];
    const float* conv_b = (const float*)d_in[4];
    const float* tbase  = (const float*)d_in[5];
    const float* trs    = (const float*)d_in[6];
    const float* decay  = (const float*)d_in[7];
    const float* anchor = (const float*)d_in[8];
    const float* score  = (const float*)d_in[9];
    const float* nscale = (const float*)d_in[10];
    const float* Wre    = (const float*)d_in[11];
    const float* Wim    = (const float*)d_in[12];
    const float* Wout   = (const float*)d_in[13];
    float* out = (float*)d_out;

    // GEMM1: z = x @ W_in   (C -> g_Z via selA=0)
    sgemm128<<<dim3((TOT + 127)/128, ROWS/128), 256>>>(x, W_in, nullptr, 0,
                                                       ROWS, TOT, DIM);
    // conv + activations + p_w + theta
    conv_act_kernel<<<dim3((TOT + 255)/256, ROWS), 256>>>(mask, conv_w, conv_b,
                                                          tbase, trs, decay,
                                                          anchor, score);
    // chunked scan (pass1 stores merged terms; pass3 streams them back)
    scan_pass1<<<NUNIT/8, 256>>>();
    scan_pass2<<<BATCH*KH, 288>>>();
    scan_pass3<<<NUNIT/8, 256>>>(nscale);
    // projection + gate
    gemm2_kernel<<<R2/128, 256>>>(Wre, Wim);
    // GEMM3: out = (y*gate) @ W_out   (A -> g_YG via selA=1)
    sgemm128<<<dim3(DIM/128, ROWS/128), 256>>>(nullptr, Wout, out, 1,
                                               ROWS, DIM, DIM);
}

// round 14
// speedup vs baseline: 1.0797x; 1.0797x over previous
#include <cuda_runtime.h>
#include <math.h>

#define BATCH 2
#define LEN   2048
#define DIM   1024
#define KH    32
#define MM    4
#define HH    32
#define AHN   4
#define DHN   28
#define CKN   4
#define TOT   2208
#define ROWS  (BATCH*LEN)          // 4096
#define NCH   64                   // chunks along L
#define LCH   32                   // chunk length
#define NUNIT (BATCH*KH*NCH)       // 4096 warp units
#define CSS   260                  // chunk-state stride (256 re/im + den + pad)
#define R2    (ROWS*KH)            // 131072 rows for GEMM2
#define PI3   1.0471975511965976f

typedef unsigned long long u64;

// ---------------- scratch (device globals; no cudaMalloc allowed) ------------
static __device__ float g_Z[ROWS*TOT];        // 36.2 MB  post-GEMM1 / pre-conv
static __device__ float g_XV[ROWS*DIM];       // 16.8 MB  x_val
static __device__ float g_GATE[ROWS*DIM];     // 16.8 MB  silu gate
static __device__ float g_PW[ROWS*KH];        //  0.5 MB  p * time_weight
static __device__ float g_TH[ROWS*KH*MM];     //  2.1 MB  theta_dyn
static __device__ float g_CS[NUNIT*CSS];      //  4.3 MB  chunk sums / offsets
static __device__ float g_RENIM[(size_t)R2*256];     // 134 MB normalized [ren|imn]
static __device__ float g_YG[ROWS*DIM];       // 16.8 MB  y1 * gate

// ---------------- f32x2 packed-FMA helpers (PTX, sm_100+ base family) --------
__device__ __forceinline__ u64 pk2(float x, float y) {
    u64 r;
    asm("mov.b64 %0, {%1, %2};" : "=l"(r) : "f"(x), "f"(y));
    return r;
}
__device__ __forceinline__ void ffma2(u64& d, u64 a, u64 b) {
    asm("fma.rn.f32x2 %0, %1, %2, %0;" : "+l"(d) : "l"(a), "l"(b));
}
__device__ __forceinline__ float2 up2(u64 v) {
    float2 f;
    asm("mov.b64 {%0, %1}, %2;" : "=f"(f.x), "=f"(f.y) : "l"(v));
    return f;
}

// ---------------- SGEMM 128x128x8, 256 thr, 8x8 microtile, f32x2 core --------
// selA==0 : A = Ain (param),  C = g_Z     (GEMM1: x @ W_in)
// selA==1 : A = g_YG,         C = Cin     (GEMM3: (y*gate) @ W_out)
// Accumulators paired over the i (row) axis: acc2[ip][j] = {acc[2ip][j], acc[2ip+1][j]}
__global__ __launch_bounds__(256, 2)
void sgemm128(const float* __restrict__ Ain, const float* __restrict__ B,
              float* __restrict__ Cin, int selA, int M, int N, int Kd)
{
    const float* A = selA ? (const float*)g_YG : Ain;
    float*       C = selA ? Cin : (float*)g_Z;

    __shared__ float As[2][8][128];
    __shared__ float Bs[2][8][128];

    const int tid = threadIdx.x;
    const int bm  = blockIdx.y * 128;
    const int bn  = blockIdx.x * 128;

    const int arow = tid >> 1;          // 0..127
    const int acol = (tid & 1) << 2;    // 0 or 4
    const int brow = tid >> 5;          // 0..7
    const int bcol = (tid & 31) << 2;   // 0..124

    const int tx = tid & 15;
    const int ty = tid >> 4;

    const float* Ag = A + (size_t)(bm + arow) * Kd + acol;
    const float* Bg = B + (size_t)brow * N + bn + bcol;
    const bool bvalid = (bn + bcol) < N;

    u64 acc2[4][8];
#pragma unroll
    for (int ip = 0; ip < 4; ip++)
#pragma unroll
        for (int j = 0; j < 8; j++) acc2[ip][j] = 0ull;

    float4 aR = *(const float4*)Ag;
    float4 bR = bvalid ? *(const float4*)Bg : make_float4(0.f,0.f,0.f,0.f);

    int buf = 0;
    As[0][acol+0][arow] = aR.x;
    As[0][acol+1][arow] = aR.y;
    As[0][acol+2][arow] = aR.z;
    As[0][acol+3][arow] = aR.w;
    *(float4*)&Bs[0][brow][bcol] = bR;
    __syncthreads();

    const int nk = Kd >> 3;
    for (int kt = 0; kt < nk; kt++) {
        if (kt + 1 < nk) {
            aR = *(const float4*)(Ag + (kt + 1) * 8);
            bR = bvalid ? *(const float4*)(Bg + (size_t)(kt + 1) * 8 * N)
                        : make_float4(0.f,0.f,0.f,0.f);
        }
#pragma unroll
        for (int kk = 0; kk < 8; kk++) {
            float4 a0 = *(const float4*)&As[buf][kk][ty*8];
            float4 a1 = *(const float4*)&As[buf][kk][ty*8+4];
            float4 b0 = *(const float4*)&Bs[buf][kk][tx*8];
            float4 b1 = *(const float4*)&Bs[buf][kk][tx*8+4];
            // A row-pairs (adjacent floats -> one 64-bit lane pair)
            u64 ap[4] = { pk2(a0.x, a0.y), pk2(a0.z, a0.w),
                          pk2(a1.x, a1.y), pk2(a1.z, a1.w) };
            // B broadcast-duplicated per column
            u64 bd[8] = { pk2(b0.x, b0.x), pk2(b0.y, b0.y),
                          pk2(b0.z, b0.z), pk2(b0.w, b0.w),
                          pk2(b1.x, b1.x), pk2(b1.y, b1.y),
                          pk2(b1.z, b1.z), pk2(b1.w, b1.w) };
#pragma unroll
            for (int ip = 0; ip < 4; ip++)
#pragma unroll
                for (int j = 0; j < 8; j++)
                    ffma2(acc2[ip][j], ap[ip], bd[j]);
        }
        if (kt + 1 < nk) {
            int nb = buf ^ 1;
            As[nb][acol+0][arow] = aR.x;
            As[nb][acol+1][arow] = aR.y;
            As[nb][acol+2][arow] = aR.z;
            As[nb][acol+3][arow] = aR.w;
            *(float4*)&Bs[nb][brow][bcol] = bR;
            __syncthreads();
            buf = nb;
        }
    }

#pragma unroll
    for (int ip = 0; ip < 4; ip++) {
        float2 c[8];
#pragma unroll
        for (int j = 0; j < 8; j++) c[j] = up2(acc2[ip][j]);
        int row0 = bm + ty*8 + 2*ip;
        float* Cp0 = C + (size_t)row0 * N + bn + tx*8;
        float* Cp1 = Cp0 + N;
        if (bn + tx*8 < N) {
            *(float4*)Cp0 = make_float4(c[0].x, c[1].x, c[2].x, c[3].x);
            *(float4*)Cp1 = make_float4(c[0].y, c[1].y, c[2].y, c[3].y);
        }
        if (bn + tx*8 + 4 < N) {
            *(float4*)(Cp0+4) = make_float4(c[4].x, c[5].x, c[6].x, c[7].x);
            *(float4*)(Cp1+4) = make_float4(c[4].y, c[5].y, c[6].y, c[7].y);
        }
    }
}

// ---------------- conv(CK=4) + activations + routing ------------------------
__global__ void conv_act_kernel(const float* __restrict__ mask,
        const float* __restrict__ conv_w, const float* __restrict__ conv_b,
        const float* __restrict__ tbase,  const float* __restrict__ trs,
        const float* __restrict__ decay,  const float* __restrict__ anchor,
        const float* __restrict__ score)
{
    int c = blockIdx.x * blockDim.x + threadIdx.x;
    int r = blockIdx.y;
    if (c >= TOT) return;
    int l = r & (LEN - 1);

    float acc = conv_b[c];
#pragma unroll
    for (int t = 0; t < CKN; t++) {
        int ls = l - (CKN - 1) + t;
        if (ls >= 0)
            acc = fmaf(g_Z[(size_t)(r - (CKN - 1) + t) * TOT + c],
                       conv_w[t * TOT + c], acc);
    }
    float mk = mask[r];

    if (c < DIM) {
        g_XV[(size_t)r * DIM + c] = acc * mk;
    } else if (c < 2*DIM) {
        float sg = 1.0f / (1.0f + __expf(-acc));
        g_GATE[(size_t)r * DIM + (c - DIM)] = acc * sg;
    } else if (c < 2*DIM + KH) {
        int k = c - 2*DIM;
        float ss = acc * mk;
        float sc = score[k] * ss;
        sc = fminf(fmaxf(sc, -20.0f), 20.0f);
        float p = __expf(sc) * mk;
        float w;
        if (k < DHN) {
            float sl = log1pf(__expf(decay[k]));          // softplus
            w = __expf(-sl * (float)(LEN - 1 - l));
        } else {
            float sl = log1pf(__expf(anchor[k - DHN]));
            w = __expf(-sl * (float)l);
        }
        g_PW[r * KH + k] = p * w;
    } else {
        int i = c - (2*DIM + KH);                          // i = k*4 + m
        int k = i >> 2;
        float td = acc / (1.0f + fabsf(acc));
        g_TH[(size_t)r * (KH*MM) + i] = fmaf(trs[k] * td, PI3, tbase[i]);
    }
}

// ---------------- scan pass 1: chunk sums (one warp per (b,k,chunk)) --------
__global__ void scan_pass1()
{
    int wid  = threadIdx.x >> 5;
    int lane = threadIdx.x & 31;
    int u = blockIdx.x * 8 + wid;       // 0..4095
    int bk = u >> 6;
    int chunk = u & (NCH - 1);
    int b = bk >> 5;
    int k = bk & 31;
    int h = lane;

    float are[4] = {0,0,0,0}, aim[4] = {0,0,0,0}, ad = 0.f;
    int l0 = chunk * LCH;
    const float* xvp = g_XV + (size_t)(b*LEN + l0) * DIM + k*HH + h;
    const float* thp = g_TH + (size_t)(b*LEN + l0) * (KH*MM) + k*MM;
    const float* pwp = g_PW + (size_t)(b*LEN + l0) * KH + k;

    for (int i = 0; i < LCH; i++) {
        float xv = xvp[(size_t)i * DIM];
        float4 th = *(const float4*)(thp + (size_t)i * (KH*MM));
        float pw = pwp[(size_t)i * KH];
        float s, c;
        __sincosf(xv*th.x, &s, &c); are[0]=fmaf(pw,c,are[0]); aim[0]=fmaf(pw,s,aim[0]);
        __sincosf(xv*th.y, &s, &c); are[1]=fmaf(pw,c,are[1]); aim[1]=fmaf(pw,s,aim[1]);
        __sincosf(xv*th.z, &s, &c); are[2]=fmaf(pw,c,are[2]); aim[2]=fmaf(pw,s,aim[2]);
        __sincosf(xv*th.w, &s, &c); are[3]=fmaf(pw,c,are[3]); aim[3]=fmaf(pw,s,aim[3]);
        ad += pw;
    }
    float* cs = g_CS + (size_t)u * CSS;
    *(float4*)(cs + h*4)       = make_float4(are[0],are[1],are[2],are[3]);
    *(float4*)(cs + 128 + h*4) = make_float4(aim[0],aim[1],aim[2],aim[3]);
    if (h == 0) cs[256] = ad;
}

// ---------------- scan pass 2: exclusive prefix over chunks (MLP) -----------
__global__ void scan_pass2()
{
    int bk = blockIdx.x;       // 0..63
    int j  = threadIdx.x;      // channel 0..256 (256 = den)
    if (j >= 257) return;
    float s = 0.f;
    float* base = g_CS + (size_t)bk * NCH * CSS + j;
#pragma unroll
    for (int c0 = 0; c0 < NCH; c0 += 8) {
        float v[8];
#pragma unroll
        for (int i = 0; i < 8; i++) v[i] = base[(size_t)(c0 + i) * CSS];
#pragma unroll
        for (int i = 0; i < 8; i++) {
            float t = v[i];
            base[(size_t)(c0 + i) * CSS] = s;
            s += t;
        }
    }
}

// ---------------- scan pass 3: emit normalized [ren|imn] --------------------
__global__ void scan_pass3(const float* __restrict__ nscale)
{
    int wid  = threadIdx.x >> 5;
    int lane = threadIdx.x & 31;
    int u = blockIdx.x * 8 + wid;
    int bk = u >> 6;
    int chunk = u & (NCH - 1);
    int b = bk >> 5;
    int k = bk & 31;
    int h = lane;

    float* cs = g_CS + (size_t)u * CSS;
    float4 r4 = *(const float4*)(cs + h*4);
    float4 i4 = *(const float4*)(cs + 128 + h*4);
    float are[4] = {r4.x, r4.y, r4.z, r4.w};
    float aim[4] = {i4.x, i4.y, i4.z, i4.w};
    float ad = cs[256];

    float4 nsr = *(const float4*)(nscale + h*4);
    float4 nsi = *(const float4*)(nscale + 128 + h*4);

    int l0 = chunk * LCH;
    const float* xvp = g_XV + (size_t)(b*LEN + l0) * DIM + k*HH + h;
    const float* thp = g_TH + (size_t)(b*LEN + l0) * (KH*MM) + k*MM;
    const float* pwp = g_PW + (size_t)(b*LEN + l0) * KH + k;

    for (int i = 0; i < LCH; i++) {
        int l = l0 + i;
        float xv = xvp[(size_t)i * DIM];
        float4 th = *(const float4*)(thp + (size_t)i * (KH*MM));
        float pw = pwp[(size_t)i * KH];
        float s, c;
        __sincosf(xv*th.x, &s, &c); are[0]=fmaf(pw,c,are[0]); aim[0]=fmaf(pw,s,aim[0]);
        __sincosf(xv*th.y, &s, &c); are[1]=fmaf(pw,c,are[1]); aim[1]=fmaf(pw,s,aim[1]);
        __sincosf(xv*th.z, &s, &c); are[2]=fmaf(pw,c,are[2]); aim[2]=fmaf(pw,s,aim[2]);
        __sincosf(xv*th.w, &s, &c); are[3]=fmaf(pw,c,are[3]); aim[3]=fmaf(pw,s,aim[3]);
        ad += pw;

        float invd = __fdividef(1.0f, fmaxf(ad, 1e-4f));
        float re0 = are[0]*invd, re1 = are[1]*invd, re2 = are[2]*invd, re3 = are[3]*invd;
        float im0 = aim[0]*invd, im1 = aim[1]*invd, im2 = aim[2]*invd, im3 = aim[3]*invd;

        float msq = re0*re0;
        msq = fmaf(re1,re1,msq); msq = fmaf(re2,re2,msq); msq = fmaf(re3,re3,msq);
        msq = fmaf(im0,im0,msq); msq = fmaf(im1,im1,msq);
        msq = fmaf(im2,im2,msq); msq = fmaf(im3,im3,msq);
#pragma unroll
        for (int off = 16; off >= 1; off >>= 1)
            msq += __shfl_xor_sync(0xffffffffu, msq, off);
        float rsq = rsqrtf(msq * (1.0f/256.0f) + 1e-5f);

        float* outp = g_RENIM + ((size_t)(b*LEN + l) * KH + k) * 256;
        *(float4*)(outp + h*4) = make_float4(re0*rsq*nsr.x, re1*rsq*nsr.y,
                                             re2*rsq*nsr.z, re3*rsq*nsr.w);
        *(float4*)(outp + 128 + h*4) = make_float4(im0*rsq*nsi.x, im1*rsq*nsi.y,
                                                   im2*rsq*nsi.z, im3*rsq*nsi.w);
    }
}

// ---------------- GEMM2: [ren|imn](131072x256) @ [Wre;Wim](256x32), *gate ---
__global__ __launch_bounds__(256)
void gemm2_kernel(const float* __restrict__ Wre, const float* __restrict__ Wim)
{
    __shared__ float Ws[256*32];     // full stacked weight, 32 KB
    __shared__ float As[128*36];     // 128 rows x 32 k, padded

    int tid = threadIdx.x;
    int row0 = blockIdx.x * 128;

    for (int i = tid*4; i < 8192; i += 1024) {
        float4 v = (i < 4096) ? *(const float4*)(Wre + i)
                              : *(const float4*)(Wim + i - 4096);
        *(float4*)&Ws[i] = v;
    }

    int lrow = tid & 127;
    int kq   = tid >> 7;       // 0..1
    int tx   = tid & 7;        // col group: cols tx*4..+3
    int trow = tid >> 3;       // 0..31 -> rows trow*4..+3

    float acc[4][4];
#pragma unroll
    for (int e = 0; e < 4; e++)
#pragma unroll
        for (int q = 0; q < 4; q++) acc[e][q] = 0.0f;

    const float* Ag = g_RENIM + (size_t)(row0 + lrow) * 256;
    __syncthreads();

    for (int kc = 0; kc < 8; kc++) {
#pragma unroll
        for (int q = 0; q < 4; q++) {
            int kidx = kq*4 + q;                       // 0..7
            float4 v = *(const float4*)(Ag + kc*32 + kidx*4);
            *(float4*)&As[lrow*36 + kidx*4] = v;
        }
        __syncthreads();
#pragma unroll
        for (int kk = 0; kk < 32; kk++) {
            float4 w = *(const float4*)&Ws[(kc*32 + kk)*32 + tx*4];
            float a0 = As[(trow*4+0)*36 + kk];
            float a1 = As[(trow*4+1)*36 + kk];
            float a2 = As[(trow*4+2)*36 + kk];
            float a3 = As[(trow*4+3)*36 + kk];
            acc[0][0]=fmaf(a0,w.x,acc[0][0]); acc[0][1]=fmaf(a0,w.y,acc[0][1]);
            acc[0][2]=fmaf(a0,w.z,acc[0][2]); acc[0][3]=fmaf(a0,w.w,acc[0][3]);
            acc[1][0]=fmaf(a1,w.x,acc[1][0]); acc[1][1]=fmaf(a1,w.y,acc[1][1]);
            acc[1][2]=fmaf(a1,w.z,acc[1][2]); acc[1][3]=fmaf(a1,w.w,acc[1][3]);
            acc[2][0]=fmaf(a2,w.x,acc[2][0]); acc[2][1]=fmaf(a2,w.y,acc[2][1]);
            acc[2][2]=fmaf(a2,w.z,acc[2][2]); acc[2][3]=fmaf(a2,w.w,acc[2][3]);
            acc[3][0]=fmaf(a3,w.x,acc[3][0]); acc[3][1]=fmaf(a3,w.y,acc[3][1]);
            acc[3][2]=fmaf(a3,w.z,acc[3][2]); acc[3][3]=fmaf(a3,w.w,acc[3][3]);
        }
        __syncthreads();
    }

#pragma unroll
    for (int e = 0; e < 4; e++) {
        size_t R = (size_t)row0 + trow*4 + e;
        float4 g = *(const float4*)(g_GATE + R*32 + tx*4);   // gate, flat view
        *(float4*)(g_YG + R*32 + tx*4) =
            make_float4(acc[e][0]*g.x, acc[e][1]*g.y, acc[e][2]*g.z, acc[e][3]*g.w);
    }
}

// ---------------- launch -----------------------------------------------------
extern "C" void kernel_launch(void* const* d_in, const int* in_sizes, int n_in,
                              void* d_out, int out_size)
{
    (void)in_sizes; (void)n_in; (void)out_size;
    const float* x      = (const float*)d_in[0];
    const float* mask   = (const float*)d_in[1];
    const float* W_in   = (const float*)d_in[2];
    const float* conv_w = (const float*)d_in[3];
    const float* conv_b = (const float*)d_in[4];
    const float* tbase  = (const float*)d_in[5];
    const float* trs    = (const float*)d_in[6];
    const float* decay  = (const float*)d_in[7];
    const float* anchor = (const float*)d_in[8];
    const float* score  = (const float*)d_in[9];
    const float* nscale = (const float*)d_in[10];
    const float* Wre    = (const float*)d_in[11];
    const float* Wim    = (const float*)d_in[12];
    const float* Wout   = (const float*)d_in[13];
    float* out = (float*)d_out;

    // GEMM1: z = x @ W_in   (C -> g_Z via selA=0)
    sgemm128<<<dim3((TOT + 127)/128, ROWS/128), 256>>>(x, W_in, nullptr, 0,
                                                       ROWS, TOT, DIM);
    // conv + activations + p_w + theta
    conv_act_kernel<<<dim3((TOT + 255)/256, ROWS), 256>>>(mask, conv_w, conv_b,
                                                          tbase, trs, decay,
                                                          anchor, score);
    // chunked scan
    scan_pass1<<<NUNIT/8, 256>>>();
    scan_pass2<<<BATCH*KH, 288>>>();
    scan_pass3<<<NUNIT/8, 256>>>(nscale);
    // projection + gate
    gemm2_kernel<<<R2/128, 256>>>(Wre, Wim);
    // GEMM3: out = (y*gate) @ W_out   (A -> g_YG via selA=1)
    sgemm128<<<dim3(DIM/128, ROWS/128), 256>>>(nullptr, Wout, out, 1,
                                               ROWS, DIM, DIM);
}